// round 10
// baseline (speedup 1.0000x reference)
#include <cuda_runtime.h>
#include <cuda_fp16.h>
#include <cstdint>

// ---------------------------------------------------------------------------
// TransformerAgent: 4-layer FAVOR+ transformer.
// GEMMs: fp16 mma.sync; A via cp.async+ldmatrix (BK=64, 3-stage), B weights
// pre-swizzled into mma fragment layout fed by LDG.128. 128x128 tile,
// 64x32 warp tile, 2 CTAs/SM. FAVOR kv+num fused per (b,h) block.
// Layer 3: token-0 rows only.
// ---------------------------------------------------------------------------

#define Bc 64
#define Sc 512
#define SP 513
#define Dc 512
#define Hc 8
#define HDc 64
#define Fc 2048
#define Lc 4
#define Ac 16
#define OBSc 128
#define Tc (Bc * SP)          // 32832 tokens
#define QS (3 * Dc)           // fused qkv row stride = 1536

#define KEPS 1e-3f
#define LNEPS 1e-6f

typedef __half fp16;

// ------------------------- scratch (static device) ------------------------
__device__ float g_x  [Tc * Dc];
__device__ fp16  g_xh [Tc * Dc];
__device__ fp16  g_qkv[Tc * QS];
__device__ fp16  g_ah [Tc * Dc];
__device__ float g_tmp[Tc * Dc];
__device__ fp16  g_fh [Tc * Fc];
__device__ fp16  g_ih [Bc * Sc * OBSc];
// layer-3 compact (token-0 rows only)
__device__ float g_x0  [Bc * Dc];
__device__ fp16  g_xh0 [Bc * Dc];
__device__ fp16  g_xg0 [Bc * Dc];
__device__ float g_q0  [Bc * Dc];
__device__ fp16  g_ah0 [Bc * Dc];
__device__ float g_tmp0[Bc * Dc];
__device__ fp16  g_fh0 [Bc * Fc];
// weights in mma B-fragment layout (ntPair-major), fp16
__device__ fp16  g_wqkv[Lc * QS * Dc];
__device__ float g_bqkv[Lc * QS];
__device__ fp16  g_wo [Lc * Dc * Dc];
__device__ fp16  g_w1 [Lc * Fc * Dc];
__device__ fp16  g_w2 [Lc * Dc * Fc];
__device__ fp16  g_we [Dc * OBSc];

// --------------------------- PTX helpers -----------------------------------
__device__ __forceinline__ uint32_t smem_u32(const void* p) {
    uint32_t a;
    asm("{ .reg .u64 t; cvta.to.shared.u64 t, %1; cvt.u32.u64 %0, t; }"
        : "=r"(a) : "l"(p));
    return a;
}

#define CP_ASYNC16(s, g) \
    asm volatile("cp.async.ca.shared.global [%0], [%1], 16;" :: "r"(s), "l"(g))
#define CP_COMMIT() asm volatile("cp.async.commit_group;" ::: "memory")
#define CP_WAIT1()  asm volatile("cp.async.wait_group 1;" ::: "memory")

#define LDSM4(r, a) \
    asm volatile("ldmatrix.sync.aligned.m8n8.x4.shared.b16 {%0,%1,%2,%3}, [%4];" \
        : "=r"((r)[0]), "=r"((r)[1]), "=r"((r)[2]), "=r"((r)[3]) : "r"(a))

#define MMA16816(d, a, b0, b1) \
    asm volatile("mma.sync.aligned.m16n8k16.row.col.f32.f16.f16.f32 " \
        "{%0,%1,%2,%3},{%4,%5,%6,%7},{%8,%9},{%0,%1,%2,%3};" \
        : "+f"((d)[0]), "+f"((d)[1]), "+f"((d)[2]), "+f"((d)[3]) \
        : "r"((a)[0]), "r"((a)[1]), "r"((a)[2]), "r"((a)[3]), "r"(b0), "r"(b1))

// ---------------------------------------------------------------------------
// fp16 GEMM: C[M,N] = A[M,K] @ W^T + bias, W pre-swizzled in B-frag layout:
//   uint4 index = (ntPair * (K/16) + kt) * 32 + lane.
// Block 128x128 (grid.x = m-blocks, grid.y = n-blocks), 8 warps 64x32,
// A: BK=64 chunks, 3-stage cp.async + ldmatrix, one barrier per chunk.
// smem row stride 144 B (64 halves + pad) -> conflict-free ldmatrix.
// ---------------------------------------------------------------------------
#define GROW   144
#define GARR   (128 * GROW)       // 18432 B per stage
#define NSTAGE 3
#define GSMEM  (NSTAGE * GARR)    // 55296 B

__global__ __launch_bounds__(256, 2)
void gemm_mma(const fp16* __restrict__ A, const fp16* __restrict__ W,
              const float* __restrict__ bias,
              float* __restrict__ Cf, fp16* __restrict__ Ch,
              int M, int N, int K, int ldc, int relu, int rowmap)
{
    extern __shared__ char smem[];
    const uint32_t sbase = smem_u32(smem);
    const int tid  = threadIdx.x;
    const int wid  = tid >> 5;
    const int lane = tid & 31;
    const int m0 = blockIdx.x * 128;
    const int n0 = blockIdx.y * 128;
    const int nch = K >> 6;
    const int ktiles = K >> 4;

    const int wm = wid >> 2;          // 0..1
    const int wn = wid & 3;           // 0..3
    const uint4* __restrict__ Wq = (const uint4*)W;
    const size_t ntp0 = (size_t)((n0 >> 4) + wn * 2);

    float acc[4][4][4];
#pragma unroll
    for (int a = 0; a < 4; a++)
#pragma unroll
        for (int b = 0; b < 4; b++)
#pragma unroll
            for (int c = 0; c < 4; c++) acc[a][b][c] = 0.f;

    auto load_chunk = [&](int c) {
        const int s = c % NSTAGE;
        const size_t kb = (size_t)c * 64;
        const uint32_t sA = sbase + s * GARR;
#pragma unroll
        for (int it = 0; it < 4; it++) {
            int i = tid + it * 256;            // 0..1023
            int row = i >> 3;
            int c8  = (i & 7) * 8;
            int gr = min(m0 + row, M - 1);
            CP_ASYNC16(sA + row * GROW + (i & 7) * 16,
                       (const char*)(A + (size_t)gr * K + kb + c8));
        }
        CP_COMMIT();
    };

    load_chunk(0);
    if (nch > 1) load_chunk(1); else CP_COMMIT();

    for (int c = 0; c < nch; c++) {
        const int s = c % NSTAGE;
        CP_WAIT1();          // chunk c retired (c+1 may stay in flight)
        __syncthreads();     // everyone done computing c-1, data of c visible

        if (c + 2 < nch) load_chunk(c + 2); else CP_COMMIT();

        const uint32_t sA = sbase + s * GARR;

#pragma unroll
        for (int ks = 0; ks < 4; ks++) {
            const int kt = c * 4 + ks;
            uint4 bf0 = Wq[(ntp0       * ktiles + kt) * 32 + lane];
            uint4 bf1 = Wq[((ntp0 + 1) * ktiles + kt) * 32 + lane];
            uint32_t af[4][4];
            {
                const int r  = lane & 15;
                const int kh = (lane >> 4) * 8;
                const uint32_t kofs = (ks * 16 + kh) * 2;
#pragma unroll
                for (int mi = 0; mi < 4; mi++)
                    LDSM4(af[mi], sA + (wm * 64 + mi * 16 + r) * GROW + kofs);
            }
#pragma unroll
            for (int mi = 0; mi < 4; mi++) {
                MMA16816(acc[mi][0], af[mi], bf0.x, bf0.y);
                MMA16816(acc[mi][1], af[mi], bf0.z, bf0.w);
                MMA16816(acc[mi][2], af[mi], bf1.x, bf1.y);
                MMA16816(acc[mi][3], af[mi], bf1.z, bf1.w);
            }
        }
    }

    // ---- epilogue ----
    const int rq = lane >> 2;
    const int cq = (lane & 3) * 2;
#pragma unroll
    for (int mi = 0; mi < 4; mi++) {
#pragma unroll
        for (int half = 0; half < 2; half++) {
            int rr = m0 + wm * 64 + mi * 16 + rq + half * 8;
            if (rr >= M) continue;
            size_t orow = rowmap ? (size_t)(rr + rr / Sc + 1) : (size_t)rr;
#pragma unroll
            for (int nj = 0; nj < 4; nj++) {
                int cc = n0 + wn * 32 + nj * 8 + cq;
                float v0 = acc[mi][nj][half * 2 + 0] + bias[cc];
                float v1 = acc[mi][nj][half * 2 + 1] + bias[cc + 1];
                if (relu) { v0 = fmaxf(v0, 0.f); v1 = fmaxf(v1, 0.f); }
                if (Cf)
                    *(float2*)(Cf + orow * (size_t)ldc + cc) = make_float2(v0, v1);
                if (Ch) {
                    __half2 hp = __floats2half2_rn(v0, v1);
                    *(__half2*)(Ch + orow * (size_t)ldc + cc) = hp;
                }
            }
        }
    }
}

// ----- batched weight transpose + fp16 + B-fragment swizzle ----------------
struct WJob { const float* src; fp16* dst; int K; int N; };
struct WJobs { WJob j[25]; };

__global__ void wconv_all(WJobs jobs)
{
    WJob jb = jobs.j[blockIdx.z];
    int nbx = jb.N >> 5;
    int nb  = nbx * (jb.K >> 5);
    int bid = blockIdx.x;
    if (bid >= nb) return;
    int x = (bid % nbx) * 32;
    int y = (bid / nbx) * 32;

    __shared__ float t[32][33];
#pragma unroll
    for (int r = 0; r < 4; r++) {
        int row = y + threadIdx.y + r * 8;
        t[threadIdx.y + r * 8][threadIdx.x] = jb.src[(size_t)row * jb.N + x + threadIdx.x];
    }
    __syncthreads();
    int ktiles = jb.K >> 4;
#pragma unroll
    for (int r = 0; r < 4; r++) {
        int n = x + threadIdx.y + r * 8;
        int k = y + threadIdx.x;
        float v = t[threadIdx.x][threadIdx.y + r * 8];
        int k0 = k & 15;
        int lane = ((n & 7) << 2) | ((k0 >> 1) & 3);
        int sub  = ((n >> 3) & 1) * 4 + ((k0 >= 8) ? 2 : 0) + (k0 & 1);
        size_t idx = (((size_t)(n >> 4) * ktiles + (k >> 4)) * 32 + lane) * 8 + sub;
        jb.dst[idx] = __float2half_rn(v);
    }
}

// ------------------ pack qkv biases: [L][3*D] ------------------------------
__global__ void bpack(const float* __restrict__ bq, const float* __restrict__ bk,
                      const float* __restrict__ bv, float* __restrict__ dst)
{
    int l = blockIdx.x;
    int i = threadIdx.x;
    dst[l * QS + i]          = bq[l * Dc + i];
    dst[l * QS + Dc + i]     = bk[l * Dc + i];
    dst[l * QS + 2 * Dc + i] = bv[l * Dc + i];
}

// --------------------- fp32 -> fp16 convert (flat) --------------------------
__global__ void fcvt(const float* __restrict__ src, fp16* __restrict__ dst, int n4)
{
    int i = blockIdx.x * 256 + threadIdx.x;
    if (i < n4) {
        float4 v = ((const float4*)src)[i];
        __half2 a = __floats2half2_rn(v.x, v.y);
        __half2 b = __floats2half2_rn(v.z, v.w);
        uint2 o;
        o.x = *(uint32_t*)&a;
        o.y = *(uint32_t*)&b;
        ((uint2*)dst)[i] = o;
    }
}

// --------------------- init: hidden-state row per batch -------------------
__global__ void init_h0(const float* __restrict__ hs, const void* __restrict__ resets,
                        float* __restrict__ x, fp16* __restrict__ xh)
{
    __shared__ int mode;
    int b = blockIdx.x;
    if (threadIdx.x == 0) {
        const unsigned int* w = (const unsigned int*)resets;
        bool allint = true, allflt = true;
        for (int i = 0; i < 16; i++) {
            unsigned int u = w[i];
            if (u != 0u && u != 1u) allint = false;
            if (u != 0u && u != 0x3F800000u) allflt = false;
        }
        mode = allint ? 0 : (allflt ? 2 : 1);
    }
    __syncthreads();
    bool rst;
    if (mode == 0)      rst = ((const int*)resets)[b] != 0;
    else if (mode == 2) rst = ((const float*)resets)[b] != 0.f;
    else                rst = ((const unsigned char*)resets)[b] != 0;

    float val = rst ? 0.f : hs[b * Dc + threadIdx.x];
    size_t o = (size_t)b * SP * Dc + threadIdx.x;
    x[o] = val;
    xh[o] = __float2half_rn(val);
}

// --------------- FAVOR fused: kv+ksum in smem, then numerator ---------------
// One block per (b,h). Phase 1: kv = sum_s pk^T outer v (smem), ksum.
// Phase 2: if q0 == null -> out for all SP tokens into ah (full layers);
//          else          -> out for token 0 only from q0 into ah0.
__global__ __launch_bounds__(256)
void favor_fused(const fp16* __restrict__ qkv,
                 const float* __restrict__ q0,
                 fp16* __restrict__ ah, fp16* __restrict__ ah0)
{
    int bh = blockIdx.x;
    int b = bh / Hc, h = bh % Hc;
    const fp16* kb = qkv + (size_t)b * SP * QS + Dc + h * HDc;
    const fp16* vb = qkv + (size_t)b * SP * QS + 2 * Dc + h * HDc;

    __shared__ float skv[HDc][HDc];   // 16 KB
    __shared__ float sks[HDc];
    __shared__ float sbuf[16][HDc];   // phase1: [0..7]=pk, [8..15]=v; phase2: pq

    int tid = threadIdx.x;
    int tm = (tid >> 4) * 4;
    int td = (tid & 15) * 4;

    float acc[4][4];
#pragma unroll
    for (int i = 0; i < 4; i++)
#pragma unroll
        for (int j = 0; j < 4; j++) acc[i][j] = 0.f;
    float ks = 0.f;

    for (int s0 = 0; s0 < SP; s0 += 8) {
        int nch = min(8, SP - s0);
        for (int i = tid; i < nch * HDc; i += 256) {
            int ss = i >> 6, dd = i & 63;
            float kk = __half2float(kb[(size_t)(s0 + ss) * QS + dd]);
            sbuf[ss][dd]     = fmaxf(kk, 0.f) + KEPS;
            sbuf[8 + ss][dd] = __half2float(vb[(size_t)(s0 + ss) * QS + dd]);
        }
        __syncthreads();
        for (int j = 0; j < nch; j++) {
            float pa[4], va[4];
#pragma unroll
            for (int i = 0; i < 4; i++) { pa[i] = sbuf[j][tm + i]; va[i] = sbuf[8 + j][td + i]; }
#pragma unroll
            for (int i = 0; i < 4; i++)
#pragma unroll
                for (int l = 0; l < 4; l++)
                    acc[i][l] = fmaf(pa[i], va[l], acc[i][l]);
            if (tid < HDc) ks += sbuf[j][tid];
        }
        __syncthreads();
    }

    // stash kv/ksum in smem
#pragma unroll
    for (int i = 0; i < 4; i++)
#pragma unroll
        for (int l = 0; l < 4; l++)
            skv[tm + i][td + l] = acc[i][l];
    if (tid < HDc) sks[tid] = ks;
    __syncthreads();

    if (q0) {
        // token-0 only
        if (tid < HDc) {
            float qv = q0[(size_t)b * Dc + h * HDc + tid];
            sbuf[0][tid] = fmaxf(qv, 0.f) + KEPS;
        }
        __syncthreads();
        if (tid < HDc) {
            int d = tid;
            float num = 0.f, den = 0.f;
#pragma unroll 8
            for (int m = 0; m < HDc; m++) {
                float pq = sbuf[0][m];
                num = fmaf(pq, skv[m][d], num);
                den = fmaf(pq, sks[m], den);
            }
            ah0[(size_t)b * Dc + h * HDc + d] = __float2half_rn(num / den);
        }
        return;
    }

    const fp16* qb = qkv + (size_t)b * SP * QS + h * HDc;
    for (int t0 = 0; t0 < SP; t0 += 16) {
        for (int i = tid; i < 16 * HDc; i += 256) {
            int tt = i >> 6, dd = i & 63;
            int s = t0 + tt;
            float qv = 0.f;
            if (s < SP) qv = __half2float(qb[(size_t)s * QS + dd]);
            sbuf[tt][dd] = fmaxf(qv, 0.f) + KEPS;
        }
        __syncthreads();

        int t = tid >> 4;
        int dq = (tid & 15) * 4;
        float a0 = 0.f, a1 = 0.f, a2 = 0.f, a3 = 0.f, den = 0.f;
#pragma unroll
        for (int m = 0; m < HDc; m++) {
            float pq = sbuf[t][m];
            den = fmaf(pq, sks[m], den);
            float4 kk = *(const float4*)&skv[m][dq];
            a0 = fmaf(pq, kk.x, a0);
            a1 = fmaf(pq, kk.y, a1);
            a2 = fmaf(pq, kk.z, a2);
            a3 = fmaf(pq, kk.w, a3);
        }
        int s = t0 + t;
        if (s < SP) {
            float inv = 1.f / den;
            __half2 p0 = __floats2half2_rn(a0 * inv, a1 * inv);
            __half2 p1 = __floats2half2_rn(a2 * inv, a3 * inv);
            size_t idx = ((size_t)b * SP + s) * Dc + h * HDc + dq;
            uint2 o;
            o.x = *(uint32_t*)&p0;
            o.y = *(uint32_t*)&p1;
            *(uint2*)(ah + idx) = o;
        }
        __syncthreads();
    }
}

// --------------- x = LayerNorm(a + x) * s + b  (+ fp16 out) ----------------
__global__ __launch_bounds__(128)
void add_ln(const float* __restrict__ a, float* __restrict__ x,
            fp16* __restrict__ xh,
            const float* __restrict__ s, const float* __restrict__ bb)
{
    size_t r = blockIdx.x;
    const float* ar = a + r * Dc;
    float* xr = x + r * Dc;
    int tid = threadIdx.x;

    float v[4];
    float sum = 0.f, sq = 0.f;
#pragma unroll
    for (int i = 0; i < 4; i++) {
        int c = tid + i * 128;
        v[i] = ar[c] + xr[c];
        sum += v[i];
        sq  = fmaf(v[i], v[i], sq);
    }
#pragma unroll
    for (int o = 16; o > 0; o >>= 1) {
        sum += __shfl_xor_sync(0xFFFFFFFFu, sum, o);
        sq  += __shfl_xor_sync(0xFFFFFFFFu, sq, o);
    }
    __shared__ float rs[4], rq[4];
    int w = tid >> 5;
    if ((tid & 31) == 0) { rs[w] = sum; rq[w] = sq; }
    __syncthreads();
    sum = rs[0] + rs[1] + rs[2] + rs[3];
    sq  = rq[0] + rq[1] + rq[2] + rq[3];
    float mean = sum * (1.f / Dc);
    float var  = sq * (1.f / Dc) - mean * mean;
    float inv  = rsqrtf(var + LNEPS);
#pragma unroll
    for (int i = 0; i < 4; i++) {
        int c = tid + i * 128;
        float o = (v[i] - mean) * inv * s[c] + bb[c];
        xr[c] = o;
        xh[r * Dc + c] = __float2half_rn(o);
    }
}

// ---- layer-3 compact variant: reads residual from xin (stride), compact out
__global__ __launch_bounds__(128)
void add_ln0(const float* __restrict__ a, const float* __restrict__ xin,
             size_t xin_stride, float* __restrict__ xout, fp16* __restrict__ xh,
             const float* __restrict__ s, const float* __restrict__ bb)
{
    int b = blockIdx.x;
    const float* ar = a + (size_t)b * Dc;
    const float* xr = xin + (size_t)b * xin_stride;
    int tid = threadIdx.x;

    float v[4];
    float sum = 0.f, sq = 0.f;
#pragma unroll
    for (int i = 0; i < 4; i++) {
        int c = tid + i * 128;
        v[i] = ar[c] + xr[c];
        sum += v[i];
        sq  = fmaf(v[i], v[i], sq);
    }
#pragma unroll
    for (int o = 16; o > 0; o >>= 1) {
        sum += __shfl_xor_sync(0xFFFFFFFFu, sum, o);
        sq  += __shfl_xor_sync(0xFFFFFFFFu, sq, o);
    }
    __shared__ float rs[4], rq[4];
    int w = tid >> 5;
    if ((tid & 31) == 0) { rs[w] = sum; rq[w] = sq; }
    __syncthreads();
    sum = rs[0] + rs[1] + rs[2] + rs[3];
    sq  = rq[0] + rq[1] + rq[2] + rq[3];
    float mean = sum * (1.f / Dc);
    float var  = sq * (1.f / Dc) - mean * mean;
    float inv  = rsqrtf(var + LNEPS);
#pragma unroll
    for (int i = 0; i < 4; i++) {
        int c = tid + i * 128;
        float o = (v[i] - mean) * inv * s[c] + bb[c];
        xout[(size_t)b * Dc + c] = o;
        xh[(size_t)b * Dc + c] = __float2half_rn(o);
    }
}

// ---- gather token-0 rows of xh into compact A buffer ----------------------
__global__ void gather_x0(const fp16* __restrict__ xh, fp16* __restrict__ xg0)
{
    int b = blockIdx.x;
    int i = threadIdx.x;
    ((uint32_t*)xg0)[b * (Dc / 2) + i] =
        ((const uint32_t*)(xh + (size_t)b * SP * Dc))[i];
}

// ---------------- head: copy h_out and compute q_vals ----------------------
__global__ __launch_bounds__(512)
void head_kernel(const float* __restrict__ x0, const float* __restrict__ Wqp,
                 const float* __restrict__ bqp, float* __restrict__ out)
{
    int b = blockIdx.x;
    int tid = threadIdx.x;
    const float* hr = x0 + (size_t)b * Dc;
    out[b * Dc + tid] = hr[tid];

    int w = tid >> 5, lane = tid & 31;
    float sum = 0.f;
    for (int i = lane; i < Dc; i += 32)
        sum = fmaf(hr[i], Wqp[i * Ac + w], sum);
#pragma unroll
    for (int o = 16; o > 0; o >>= 1)
        sum += __shfl_xor_sync(0xFFFFFFFFu, sum, o);
    if (lane == 0) out[Bc * Dc + b * Ac + w] = sum + bqp[w];
}

// ---------------------------------------------------------------------------
extern "C" void kernel_launch(void* const* d_in, const int* in_sizes, int n_in,
                              void* d_out, int out_size)
{
    const float* hs    = (const float*)d_in[0];
    const float* ins   = (const float*)d_in[1];
    const void*  rsts  = d_in[2];
    const float* W_emb = (const float*)d_in[3];
    const float* b_emb = (const float*)d_in[4];
    const float* Wq    = (const float*)d_in[5];
    const float* bq    = (const float*)d_in[6];
    const float* Wk    = (const float*)d_in[7];
    const float* bk    = (const float*)d_in[8];
    const float* Wv    = (const float*)d_in[9];
    const float* bv    = (const float*)d_in[10];
    const float* Wo    = (const float*)d_in[11];
    const float* bo    = (const float*)d_in[12];
    const float* ln1s  = (const float*)d_in[13];
    const float* ln1b  = (const float*)d_in[14];
    const float* ln2s  = (const float*)d_in[15];
    const float* ln2b  = (const float*)d_in[16];
    const float* W1    = (const float*)d_in[17];
    const float* b1    = (const float*)d_in[18];
    const float* W2    = (const float*)d_in[19];
    const float* b2    = (const float*)d_in[20];
    const float* Wqp   = (const float*)d_in[21];
    const float* bqp   = (const float*)d_in[22];
    float* out = (float*)d_out;

    cudaFuncSetAttribute(gemm_mma, cudaFuncAttributeMaxDynamicSharedMemorySize, GSMEM);

    float *x, *tmp, *bqkv, *x0, *q0, *tmp0;
    fp16 *xh, *qkv, *ah, *fh, *ih, *xh0, *xg0, *ah0, *fh0;
    fp16 *wqkv, *wo, *w1, *w2, *we;
    cudaGetSymbolAddress((void**)&x,    g_x);
    cudaGetSymbolAddress((void**)&xh,   g_xh);
    cudaGetSymbolAddress((void**)&qkv,  g_qkv);
    cudaGetSymbolAddress((void**)&ah,   g_ah);
    cudaGetSymbolAddress((void**)&tmp,  g_tmp);
    cudaGetSymbolAddress((void**)&fh,   g_fh);
    cudaGetSymbolAddress((void**)&ih,   g_ih);
    cudaGetSymbolAddress((void**)&x0,   g_x0);
    cudaGetSymbolAddress((void**)&xh0,  g_xh0);
    cudaGetSymbolAddress((void**)&xg0,  g_xg0);
    cudaGetSymbolAddress((void**)&q0,   g_q0);
    cudaGetSymbolAddress((void**)&ah0,  g_ah0);
    cudaGetSymbolAddress((void**)&tmp0, g_tmp0);
    cudaGetSymbolAddress((void**)&fh0,  g_fh0);
    cudaGetSymbolAddress((void**)&bqkv, g_bqkv);
    cudaGetSymbolAddress((void**)&wqkv, g_wqkv);
    cudaGetSymbolAddress((void**)&wo,   g_wo);
    cudaGetSymbolAddress((void**)&w1,   g_w1);
    cudaGetSymbolAddress((void**)&w2,   g_w2);
    cudaGetSymbolAddress((void**)&we,   g_we);

    // ins convert
    {
        int n4 = (Bc * Sc * OBSc) / 4;
        fcvt<<<(n4 + 255) / 256, 256>>>(ins, ih, n4);
    }
    // all weight conversions (transpose + fp16 + B-fragment swizzle)
    {
        WJobs jobs;
        int nj = 0;
        jobs.j[nj++] = { W_emb, we, OBSc, Dc };
        for (int l = 0; l < Lc; l++) {
            size_t od = (size_t)l * Dc * Dc;
            size_t oq = (size_t)l * QS * Dc;
            size_t o1 = (size_t)l * Fc * Dc;
            size_t o2 = (size_t)l * Dc * Fc;
            jobs.j[nj++] = { Wq + od, wqkv + oq,                       Dc, Dc };
            jobs.j[nj++] = { Wk + od, wqkv + oq + (size_t)Dc * Dc,     Dc, Dc };
            jobs.j[nj++] = { Wv + od, wqkv + oq + (size_t)2 * Dc * Dc, Dc, Dc };
            jobs.j[nj++] = { Wo + od, wo + od, Dc, Dc };
            jobs.j[nj++] = { W1 + o1, w1 + o1, Dc, Fc };
            jobs.j[nj++] = { W2 + o2, w2 + o2, Fc, Dc };
        }
        wconv_all<<<dim3(1024, 1, 25), dim3(32, 8)>>>(jobs);
    }
    // pack qkv biases
    bpack<<<Lc, Dc>>>(bq, bk, bv, bqkv);

    // embedding GEMM (grid: x=m-blocks, y=n-blocks)
    gemm_mma<<<dim3((Bc * Sc) / 128, Dc / 128), 256, GSMEM>>>(
        ih, we, b_emb, x, xh, Bc * Sc, Dc, OBSc, Dc, 0, 1);

    // hidden-state rows
    init_h0<<<Bc, Dc>>>(hs, rsts, x, xh);

    const int MB = (Tc + 127) / 128;              // 257 m-blocks
    const dim3 gQKV(MB, QS / 128);                // (257, 12)
    const dim3 gKV (MB, 1024 / 128);              // (257, 8)
    const dim3 gD  (MB, Dc / 128);                // (257, 4)
    const dim3 gF  (MB, Fc / 128);                // (257, 16)

    // ---- layers 0..2: full ----
    for (int l = 0; l < Lc - 1; l++) {
        size_t od = (size_t)l * Dc * Dc;
        size_t oq = (size_t)l * QS * Dc;
        size_t o1 = (size_t)l * Fc * Dc;
        size_t o2 = (size_t)l * Dc * Fc;

        gemm_mma<<<gQKV, 256, GSMEM>>>(xh, wqkv + oq, bqkv + l * QS,
                                       0, qkv, Tc, QS, Dc, QS, 0, 0);

        favor_fused<<<Bc * Hc, 256>>>(qkv, 0, ah, 0);

        gemm_mma<<<gD, 256, GSMEM>>>(ah, wo + od, bo + l*Dc, tmp, 0, Tc, Dc, Dc, Dc, 0, 0);
        add_ln<<<Tc, 128>>>(tmp, x, xh, ln1s + l*Dc, ln1b + l*Dc);

        gemm_mma<<<gF, 256, GSMEM>>>(xh, w1 + o1, b1 + l*Fc, 0, fh, Tc, Fc, Dc, Fc, 1, 0);
        gemm_mma<<<gD, 256, GSMEM>>>(fh, w2 + o2, b2 + l*Dc, tmp, 0, Tc, Dc, Fc, Dc, 0, 0);
        add_ln<<<Tc, 128>>>(tmp, x, xh, ln2s + l*Dc, ln2b + l*Dc);
    }

    // ---- layer 3: only token-0 rows beyond the KV projection ----
    {
        const int l = Lc - 1;
        size_t od = (size_t)l * Dc * Dc;
        size_t oq = (size_t)l * QS * Dc;
        size_t o1 = (size_t)l * Fc * Dc;
        size_t o2 = (size_t)l * Dc * Fc;

        // K,V for all tokens (n-slice of packed QKV weights)
        gemm_mma<<<gKV, 256, GSMEM>>>(xh, wqkv + oq + (size_t)Dc * Dc,
                                      bqkv + l * QS + Dc,
                                      0, qkv + Dc, Tc, 1024, Dc, QS, 0, 0);
        // Q for the 64 token-0 rows: gather + small GEMM
        gather_x0<<<Bc, 256>>>(xh, xg0);
        gemm_mma<<<dim3(1, Dc / 128), 256, GSMEM>>>(
            xg0, wqkv + oq, bqkv + l * QS, q0, 0, Bc, Dc, Dc, Dc, 0, 0);

        favor_fused<<<Bc * Hc, 256>>>(qkv, q0, 0, ah0);

        // AO on 64 rows
        gemm_mma<<<dim3(1, Dc / 128), 256, GSMEM>>>(
            ah0, wo + od, bo + l*Dc, tmp0, 0, Bc, Dc, Dc, Dc, 0, 0);
        add_ln0<<<Bc, 128>>>(tmp0, x, (size_t)SP * Dc, x0, xh0,
                             ln1s + l*Dc, ln1b + l*Dc);

        // FFN on 64 rows
        gemm_mma<<<dim3(1, Fc / 128), 256, GSMEM>>>(
            xh0, w1 + o1, b1 + l*Fc, 0, fh0, Bc, Fc, Dc, Fc, 1, 0);
        gemm_mma<<<dim3(1, Dc / 128), 256, GSMEM>>>(
            fh0, w2 + o2, b2 + l*Dc, tmp0, 0, Bc, Dc, Fc, Dc, 0, 0);
        add_ln0<<<Bc, 128>>>(tmp0, x0, (size_t)Dc, x0, xh0,
                             ln2s + l*Dc, ln2b + l*Dc);
    }

    head_kernel<<<Bc, Dc>>>(x0, Wqp, bqp, out);
}

// round 11
// speedup vs baseline: 1.1466x; 1.1466x over previous
#include <cuda_runtime.h>
#include <cuda_fp16.h>
#include <cstdint>

// ---------------------------------------------------------------------------
// TransformerAgent: 4-layer FAVOR+ transformer.
// GEMMs: fp16 mma.sync; A via cp.async+ldmatrix (BK=64, 3-stage), B weights
// pre-swizzled into mma fragment layout fed by LDG.128. 128x128 tile,
// 64x32 warp tile, 2 CTAs/SM. FAVOR unfused (kv then num, full parallelism).
// Layer 3: token-0 rows only.
// ---------------------------------------------------------------------------

#define Bc 64
#define Sc 512
#define SP 513
#define Dc 512
#define Hc 8
#define HDc 64
#define Fc 2048
#define Lc 4
#define Ac 16
#define OBSc 128
#define Tc (Bc * SP)          // 32832 tokens
#define QS (3 * Dc)           // fused qkv row stride = 1536

#define KEPS 1e-3f
#define LNEPS 1e-6f

typedef __half fp16;

// ------------------------- scratch (static device) ------------------------
__device__ float g_x  [Tc * Dc];
__device__ fp16  g_xh [Tc * Dc];
__device__ fp16  g_qkv[Tc * QS];
__device__ fp16  g_ah [Tc * Dc];
__device__ float g_tmp[Tc * Dc];
__device__ fp16  g_fh [Tc * Fc];
__device__ float g_kv [Bc * Hc * HDc * HDc];
__device__ float g_ks [Bc * Hc * HDc];
__device__ fp16  g_ih [Bc * Sc * OBSc];
// layer-3 compact (token-0 rows only)
__device__ float g_x0  [Bc * Dc];
__device__ fp16  g_xh0 [Bc * Dc];
__device__ fp16  g_xg0 [Bc * Dc];
__device__ float g_q0  [Bc * Dc];
__device__ fp16  g_ah0 [Bc * Dc];
__device__ float g_tmp0[Bc * Dc];
__device__ fp16  g_fh0 [Bc * Fc];
// weights in mma B-fragment layout (ntPair-major), fp16
__device__ fp16  g_wqkv[Lc * QS * Dc];
__device__ float g_bqkv[Lc * QS];
__device__ fp16  g_wo [Lc * Dc * Dc];
__device__ fp16  g_w1 [Lc * Fc * Dc];
__device__ fp16  g_w2 [Lc * Dc * Fc];
__device__ fp16  g_we [Dc * OBSc];

// --------------------------- PTX helpers -----------------------------------
__device__ __forceinline__ uint32_t smem_u32(const void* p) {
    uint32_t a;
    asm("{ .reg .u64 t; cvta.to.shared.u64 t, %1; cvt.u32.u64 %0, t; }"
        : "=r"(a) : "l"(p));
    return a;
}

#define CP_ASYNC16(s, g) \
    asm volatile("cp.async.ca.shared.global [%0], [%1], 16;" :: "r"(s), "l"(g))
#define CP_COMMIT() asm volatile("cp.async.commit_group;" ::: "memory")
#define CP_WAIT1()  asm volatile("cp.async.wait_group 1;" ::: "memory")

#define LDSM4(r, a) \
    asm volatile("ldmatrix.sync.aligned.m8n8.x4.shared.b16 {%0,%1,%2,%3}, [%4];" \
        : "=r"((r)[0]), "=r"((r)[1]), "=r"((r)[2]), "=r"((r)[3]) : "r"(a))

#define MMA16816(d, a, b0, b1) \
    asm volatile("mma.sync.aligned.m16n8k16.row.col.f32.f16.f16.f32 " \
        "{%0,%1,%2,%3},{%4,%5,%6,%7},{%8,%9},{%0,%1,%2,%3};" \
        : "+f"((d)[0]), "+f"((d)[1]), "+f"((d)[2]), "+f"((d)[3]) \
        : "r"((a)[0]), "r"((a)[1]), "r"((a)[2]), "r"((a)[3]), "r"(b0), "r"(b1))

// ---------------------------------------------------------------------------
// fp16 GEMM: C[M,N] = A[M,K] @ W^T + bias, W pre-swizzled in B-frag layout:
//   uint4 index = (ntPair * (K/16) + kt) * 32 + lane.
// Block 128x128 (grid.x = m-blocks, grid.y = n-blocks), 8 warps 64x32,
// A: BK=64 chunks, 3-stage cp.async + ldmatrix, one barrier per chunk.
// ---------------------------------------------------------------------------
#define GROW   144
#define GARR   (128 * GROW)       // 18432 B per stage
#define NSTAGE 3
#define GSMEM  (NSTAGE * GARR)    // 55296 B

__global__ __launch_bounds__(256, 2)
void gemm_mma(const fp16* __restrict__ A, const fp16* __restrict__ W,
              const float* __restrict__ bias,
              float* __restrict__ Cf, fp16* __restrict__ Ch,
              int M, int N, int K, int ldc, int relu, int rowmap)
{
    extern __shared__ char smem[];
    const uint32_t sbase = smem_u32(smem);
    const int tid  = threadIdx.x;
    const int wid  = tid >> 5;
    const int lane = tid & 31;
    const int m0 = blockIdx.x * 128;
    const int n0 = blockIdx.y * 128;
    const int nch = K >> 6;
    const int ktiles = K >> 4;

    const int wm = wid >> 2;          // 0..1
    const int wn = wid & 3;           // 0..3
    const uint4* __restrict__ Wq = (const uint4*)W;
    const size_t ntp0 = (size_t)((n0 >> 4) + wn * 2);

    float acc[4][4][4];
#pragma unroll
    for (int a = 0; a < 4; a++)
#pragma unroll
        for (int b = 0; b < 4; b++)
#pragma unroll
            for (int c = 0; c < 4; c++) acc[a][b][c] = 0.f;

    auto load_chunk = [&](int c) {
        const int s = c % NSTAGE;
        const size_t kb = (size_t)c * 64;
        const uint32_t sA = sbase + s * GARR;
#pragma unroll
        for (int it = 0; it < 4; it++) {
            int i = tid + it * 256;            // 0..1023
            int row = i >> 3;
            int c8  = (i & 7) * 8;
            int gr = min(m0 + row, M - 1);
            CP_ASYNC16(sA + row * GROW + (i & 7) * 16,
                       (const char*)(A + (size_t)gr * K + kb + c8));
        }
        CP_COMMIT();
    };

    load_chunk(0);
    if (nch > 1) load_chunk(1); else CP_COMMIT();

    for (int c = 0; c < nch; c++) {
        const int s = c % NSTAGE;
        CP_WAIT1();          // chunk c retired (c+1 may stay in flight)
        __syncthreads();     // everyone done computing c-1, data of c visible

        if (c + 2 < nch) load_chunk(c + 2); else CP_COMMIT();

        const uint32_t sA = sbase + s * GARR;

#pragma unroll
        for (int ks = 0; ks < 4; ks++) {
            const int kt = c * 4 + ks;
            uint4 bf0 = Wq[(ntp0       * ktiles + kt) * 32 + lane];
            uint4 bf1 = Wq[((ntp0 + 1) * ktiles + kt) * 32 + lane];
            uint32_t af[4][4];
            {
                const int r  = lane & 15;
                const int kh = (lane >> 4) * 8;
                const uint32_t kofs = (ks * 16 + kh) * 2;
#pragma unroll
                for (int mi = 0; mi < 4; mi++)
                    LDSM4(af[mi], sA + (wm * 64 + mi * 16 + r) * GROW + kofs);
            }
#pragma unroll
            for (int mi = 0; mi < 4; mi++) {
                MMA16816(acc[mi][0], af[mi], bf0.x, bf0.y);
                MMA16816(acc[mi][1], af[mi], bf0.z, bf0.w);
                MMA16816(acc[mi][2], af[mi], bf1.x, bf1.y);
                MMA16816(acc[mi][3], af[mi], bf1.z, bf1.w);
            }
        }
    }

    // ---- epilogue ----
    const int rq = lane >> 2;
    const int cq = (lane & 3) * 2;
#pragma unroll
    for (int mi = 0; mi < 4; mi++) {
#pragma unroll
        for (int half = 0; half < 2; half++) {
            int rr = m0 + wm * 64 + mi * 16 + rq + half * 8;
            if (rr >= M) continue;
            size_t orow = rowmap ? (size_t)(rr + rr / Sc + 1) : (size_t)rr;
#pragma unroll
            for (int nj = 0; nj < 4; nj++) {
                int cc = n0 + wn * 32 + nj * 8 + cq;
                float v0 = acc[mi][nj][half * 2 + 0] + bias[cc];
                float v1 = acc[mi][nj][half * 2 + 1] + bias[cc + 1];
                if (relu) { v0 = fmaxf(v0, 0.f); v1 = fmaxf(v1, 0.f); }
                if (Cf)
                    *(float2*)(Cf + orow * (size_t)ldc + cc) = make_float2(v0, v1);
                if (Ch) {
                    __half2 hp = __floats2half2_rn(v0, v1);
                    *(__half2*)(Ch + orow * (size_t)ldc + cc) = hp;
                }
            }
        }
    }
}

// ----- batched weight transpose + fp16 + B-fragment swizzle ----------------
struct WJob { const float* src; fp16* dst; int K; int N; };
struct WJobs { WJob j[25]; };

__global__ void wconv_all(WJobs jobs)
{
    WJob jb = jobs.j[blockIdx.z];
    int nbx = jb.N >> 5;
    int nb  = nbx * (jb.K >> 5);
    int bid = blockIdx.x;
    if (bid >= nb) return;
    int x = (bid % nbx) * 32;
    int y = (bid / nbx) * 32;

    __shared__ float t[32][33];
#pragma unroll
    for (int r = 0; r < 4; r++) {
        int row = y + threadIdx.y + r * 8;
        t[threadIdx.y + r * 8][threadIdx.x] = jb.src[(size_t)row * jb.N + x + threadIdx.x];
    }
    __syncthreads();
    int ktiles = jb.K >> 4;
#pragma unroll
    for (int r = 0; r < 4; r++) {
        int n = x + threadIdx.y + r * 8;
        int k = y + threadIdx.x;
        float v = t[threadIdx.x][threadIdx.y + r * 8];
        int k0 = k & 15;
        int lane = ((n & 7) << 2) | ((k0 >> 1) & 3);
        int sub  = ((n >> 3) & 1) * 4 + ((k0 >= 8) ? 2 : 0) + (k0 & 1);
        size_t idx = (((size_t)(n >> 4) * ktiles + (k >> 4)) * 32 + lane) * 8 + sub;
        jb.dst[idx] = __float2half_rn(v);
    }
}

// ------------------ pack qkv biases: [L][3*D] ------------------------------
__global__ void bpack(const float* __restrict__ bq, const float* __restrict__ bk,
                      const float* __restrict__ bv, float* __restrict__ dst)
{
    int l = blockIdx.x;
    int i = threadIdx.x;
    dst[l * QS + i]          = bq[l * Dc + i];
    dst[l * QS + Dc + i]     = bk[l * Dc + i];
    dst[l * QS + 2 * Dc + i] = bv[l * Dc + i];
}

// --------------------- fp32 -> fp16 convert (flat) --------------------------
__global__ void fcvt(const float* __restrict__ src, fp16* __restrict__ dst, int n4)
{
    int i = blockIdx.x * 256 + threadIdx.x;
    if (i < n4) {
        float4 v = ((const float4*)src)[i];
        __half2 a = __floats2half2_rn(v.x, v.y);
        __half2 b = __floats2half2_rn(v.z, v.w);
        uint2 o;
        o.x = *(uint32_t*)&a;
        o.y = *(uint32_t*)&b;
        ((uint2*)dst)[i] = o;
    }
}

// --------------------- init: hidden-state row per batch -------------------
__global__ void init_h0(const float* __restrict__ hs, const void* __restrict__ resets,
                        float* __restrict__ x, fp16* __restrict__ xh)
{
    __shared__ int mode;
    int b = blockIdx.x;
    if (threadIdx.x == 0) {
        const unsigned int* w = (const unsigned int*)resets;
        bool allint = true, allflt = true;
        for (int i = 0; i < 16; i++) {
            unsigned int u = w[i];
            if (u != 0u && u != 1u) allint = false;
            if (u != 0u && u != 0x3F800000u) allflt = false;
        }
        mode = allint ? 0 : (allflt ? 2 : 1);
    }
    __syncthreads();
    bool rst;
    if (mode == 0)      rst = ((const int*)resets)[b] != 0;
    else if (mode == 2) rst = ((const float*)resets)[b] != 0.f;
    else                rst = ((const unsigned char*)resets)[b] != 0;

    float val = rst ? 0.f : hs[b * Dc + threadIdx.x];
    size_t o = (size_t)b * SP * Dc + threadIdx.x;
    x[o] = val;
    xh[o] = __float2half_rn(val);
}

// ------------------- FAVOR: kv = sum_s pk^T outer v, ksum ------------------
__global__ __launch_bounds__(256)
void favor_kv(const fp16* __restrict__ qkv, float* __restrict__ kv,
              float* __restrict__ ksum)
{
    int bh = blockIdx.x;
    int b = bh / Hc, h = bh % Hc;
    const fp16* kb = qkv + (size_t)b * SP * QS + Dc + h * HDc;
    const fp16* vb = qkv + (size_t)b * SP * QS + 2 * Dc + h * HDc;

    __shared__ float spk[8][HDc];
    __shared__ float sv [8][HDc];

    int tid = threadIdx.x;
    int tm = (tid >> 4) * 4;
    int td = (tid & 15) * 4;

    float acc[4][4];
#pragma unroll
    for (int i = 0; i < 4; i++)
#pragma unroll
        for (int j = 0; j < 4; j++) acc[i][j] = 0.f;
    float ks = 0.f;

    for (int s0 = 0; s0 < SP; s0 += 8) {
        int nch = min(8, SP - s0);
        for (int i = tid; i < nch * HDc; i += 256) {
            int ss = i >> 6, dd = i & 63;
            float kk = __half2float(kb[(size_t)(s0 + ss) * QS + dd]);
            spk[ss][dd] = fmaxf(kk, 0.f) + KEPS;
            sv[ss][dd]  = __half2float(vb[(size_t)(s0 + ss) * QS + dd]);
        }
        __syncthreads();
        for (int j = 0; j < nch; j++) {
            float pa[4], va[4];
#pragma unroll
            for (int i = 0; i < 4; i++) { pa[i] = spk[j][tm + i]; va[i] = sv[j][td + i]; }
#pragma unroll
            for (int i = 0; i < 4; i++)
#pragma unroll
                for (int l = 0; l < 4; l++)
                    acc[i][l] = fmaf(pa[i], va[l], acc[i][l]);
            if (tid < HDc) ks += spk[j][tid];
        }
        __syncthreads();
    }

    float* kvb = kv + (size_t)bh * HDc * HDc;
#pragma unroll
    for (int i = 0; i < 4; i++)
#pragma unroll
        for (int l = 0; l < 4; l++)
            kvb[(tm + i) * HDc + td + l] = acc[i][l];
    if (tid < HDc) ksum[bh * HDc + tid] = ks;
}

// ---------- FAVOR: num = pq @ kv, den; out -> fp16 --------------------------
__global__ __launch_bounds__(256)
void favor_num(const fp16* __restrict__ qkv, const float* __restrict__ kv,
               const float* __restrict__ ksum, fp16* __restrict__ ah)
{
    int bh = blockIdx.x;
    int b = bh / Hc, h = bh % Hc;
    int t0 = blockIdx.y * 16;

    __shared__ float skv[HDc][HDc];
    __shared__ float sks[HDc];
    __shared__ float spq[16][HDc];

    int tid = threadIdx.x;
    const float* kvb = kv + (size_t)bh * HDc * HDc;
    for (int i = tid; i < (HDc * HDc) / 4; i += 256)
        ((float4*)skv)[i] = ((const float4*)kvb)[i];
    if (tid < HDc) sks[tid] = ksum[bh * HDc + tid];
    for (int i = tid; i < 16 * HDc; i += 256) {
        int tt = i >> 6, dd = i & 63;
        int s = t0 + tt;
        float qv = 0.f;
        if (s < SP) qv = __half2float(qkv[((size_t)b * SP + s) * QS + h * HDc + dd]);
        spq[tt][dd] = fmaxf(qv, 0.f) + KEPS;
    }
    __syncthreads();

    int t = tid >> 4;
    int dq = (tid & 15) * 4;
    float a0 = 0.f, a1 = 0.f, a2 = 0.f, a3 = 0.f, den = 0.f;
#pragma unroll
    for (int m = 0; m < HDc; m++) {
        float pq = spq[t][m];
        den = fmaf(pq, sks[m], den);
        float4 kk = *(const float4*)&skv[m][dq];
        a0 = fmaf(pq, kk.x, a0);
        a1 = fmaf(pq, kk.y, a1);
        a2 = fmaf(pq, kk.z, a2);
        a3 = fmaf(pq, kk.w, a3);
    }
    int s = t0 + t;
    if (s < SP) {
        float inv = 1.f / den;
        __half2 p0 = __floats2half2_rn(a0 * inv, a1 * inv);
        __half2 p1 = __floats2half2_rn(a2 * inv, a3 * inv);
        size_t idx = ((size_t)b * SP + s) * Dc + h * HDc + dq;
        uint2 o;
        o.x = *(uint32_t*)&p0;
        o.y = *(uint32_t*)&p1;
        *(uint2*)(ah + idx) = o;
    }
}

// --------------- x = LayerNorm(a + x) * s + b  (+ fp16 out) ----------------
__global__ __launch_bounds__(128)
void add_ln(const float* __restrict__ a, float* __restrict__ x,
            fp16* __restrict__ xh,
            const float* __restrict__ s, const float* __restrict__ bb)
{
    size_t r = blockIdx.x;
    const float* ar = a + r * Dc;
    float* xr = x + r * Dc;
    int tid = threadIdx.x;

    float v[4];
    float sum = 0.f, sq = 0.f;
#pragma unroll
    for (int i = 0; i < 4; i++) {
        int c = tid + i * 128;
        v[i] = ar[c] + xr[c];
        sum += v[i];
        sq  = fmaf(v[i], v[i], sq);
    }
#pragma unroll
    for (int o = 16; o > 0; o >>= 1) {
        sum += __shfl_xor_sync(0xFFFFFFFFu, sum, o);
        sq  += __shfl_xor_sync(0xFFFFFFFFu, sq, o);
    }
    __shared__ float rs[4], rq[4];
    int w = tid >> 5;
    if ((tid & 31) == 0) { rs[w] = sum; rq[w] = sq; }
    __syncthreads();
    sum = rs[0] + rs[1] + rs[2] + rs[3];
    sq  = rq[0] + rq[1] + rq[2] + rq[3];
    float mean = sum * (1.f / Dc);
    float var  = sq * (1.f / Dc) - mean * mean;
    float inv  = rsqrtf(var + LNEPS);
#pragma unroll
    for (int i = 0; i < 4; i++) {
        int c = tid + i * 128;
        float o = (v[i] - mean) * inv * s[c] + bb[c];
        xr[c] = o;
        xh[r * Dc + c] = __float2half_rn(o);
    }
}

// ---- layer-3 compact variant: reads residual from xin (stride), compact out
__global__ __launch_bounds__(128)
void add_ln0(const float* __restrict__ a, const float* __restrict__ xin,
             size_t xin_stride, float* __restrict__ xout, fp16* __restrict__ xh,
             const float* __restrict__ s, const float* __restrict__ bb)
{
    int b = blockIdx.x;
    const float* ar = a + (size_t)b * Dc;
    const float* xr = xin + (size_t)b * xin_stride;
    int tid = threadIdx.x;

    float v[4];
    float sum = 0.f, sq = 0.f;
#pragma unroll
    for (int i = 0; i < 4; i++) {
        int c = tid + i * 128;
        v[i] = ar[c] + xr[c];
        sum += v[i];
        sq  = fmaf(v[i], v[i], sq);
    }
#pragma unroll
    for (int o = 16; o > 0; o >>= 1) {
        sum += __shfl_xor_sync(0xFFFFFFFFu, sum, o);
        sq  += __shfl_xor_sync(0xFFFFFFFFu, sq, o);
    }
    __shared__ float rs[4], rq[4];
    int w = tid >> 5;
    if ((tid & 31) == 0) { rs[w] = sum; rq[w] = sq; }
    __syncthreads();
    sum = rs[0] + rs[1] + rs[2] + rs[3];
    sq  = rq[0] + rq[1] + rq[2] + rq[3];
    float mean = sum * (1.f / Dc);
    float var  = sq * (1.f / Dc) - mean * mean;
    float inv  = rsqrtf(var + LNEPS);
#pragma unroll
    for (int i = 0; i < 4; i++) {
        int c = tid + i * 128;
        float o = (v[i] - mean) * inv * s[c] + bb[c];
        xout[(size_t)b * Dc + c] = o;
        xh[(size_t)b * Dc + c] = __float2half_rn(o);
    }
}

// ---- gather token-0 rows of xh into compact A buffer ----------------------
__global__ void gather_x0(const fp16* __restrict__ xh, fp16* __restrict__ xg0)
{
    int b = blockIdx.x;
    int i = threadIdx.x;
    ((uint32_t*)xg0)[b * (Dc / 2) + i] =
        ((const uint32_t*)(xh + (size_t)b * SP * Dc))[i];
}

// ---- layer-3: attention out for token 0 only --------------------------------
__global__ __launch_bounds__(64)
void favor_num0(const float* __restrict__ q0, const float* __restrict__ kv,
                const float* __restrict__ ksum, fp16* __restrict__ ah0)
{
    int bh = blockIdx.x;
    int b = bh / Hc, h = bh % Hc;
    int d = threadIdx.x;   // 0..63

    __shared__ float spq[HDc];
    __shared__ float sks[HDc];
    float qv = q0[(size_t)b * Dc + h * HDc + d];
    spq[d] = fmaxf(qv, 0.f) + KEPS;
    sks[d] = ksum[bh * HDc + d];
    __syncthreads();

    const float* kvb = kv + (size_t)bh * HDc * HDc;
    float num = 0.f, den = 0.f;
#pragma unroll 8
    for (int m = 0; m < HDc; m++) {
        float pq = spq[m];
        num = fmaf(pq, kvb[m * HDc + d], num);
        den = fmaf(pq, sks[m], den);
    }
    ah0[(size_t)b * Dc + h * HDc + d] = __float2half_rn(num / den);
}

// ---------------- head: copy h_out and compute q_vals ----------------------
__global__ __launch_bounds__(512)
void head_kernel(const float* __restrict__ x0, const float* __restrict__ Wqp,
                 const float* __restrict__ bqp, float* __restrict__ out)
{
    int b = blockIdx.x;
    int tid = threadIdx.x;
    const float* hr = x0 + (size_t)b * Dc;
    out[b * Dc + tid] = hr[tid];

    int w = tid >> 5, lane = tid & 31;
    float sum = 0.f;
    for (int i = lane; i < Dc; i += 32)
        sum = fmaf(hr[i], Wqp[i * Ac + w], sum);
#pragma unroll
    for (int o = 16; o > 0; o >>= 1)
        sum += __shfl_xor_sync(0xFFFFFFFFu, sum, o);
    if (lane == 0) out[Bc * Dc + b * Ac + w] = sum + bqp[w];
}

// ---------------------------------------------------------------------------
extern "C" void kernel_launch(void* const* d_in, const int* in_sizes, int n_in,
                              void* d_out, int out_size)
{
    const float* hs    = (const float*)d_in[0];
    const float* ins   = (const float*)d_in[1];
    const void*  rsts  = d_in[2];
    const float* W_emb = (const float*)d_in[3];
    const float* b_emb = (const float*)d_in[4];
    const float* Wq    = (const float*)d_in[5];
    const float* bq    = (const float*)d_in[6];
    const float* Wk    = (const float*)d_in[7];
    const float* bk    = (const float*)d_in[8];
    const float* Wv    = (const float*)d_in[9];
    const float* bv    = (const float*)d_in[10];
    const float* Wo    = (const float*)d_in[11];
    const float* bo    = (const float*)d_in[12];
    const float* ln1s  = (const float*)d_in[13];
    const float* ln1b  = (const float*)d_in[14];
    const float* ln2s  = (const float*)d_in[15];
    const float* ln2b  = (const float*)d_in[16];
    const float* W1    = (const float*)d_in[17];
    const float* b1    = (const float*)d_in[18];
    const float* W2    = (const float*)d_in[19];
    const float* b2    = (const float*)d_in[20];
    const float* Wqp   = (const float*)d_in[21];
    const float* bqp   = (const float*)d_in[22];
    float* out = (float*)d_out;

    cudaFuncSetAttribute(gemm_mma, cudaFuncAttributeMaxDynamicSharedMemorySize, GSMEM);

    float *x, *tmp, *kv, *ks, *bqkv, *x0, *q0, *tmp0;
    fp16 *xh, *qkv, *ah, *fh, *ih, *xh0, *xg0, *ah0, *fh0;
    fp16 *wqkv, *wo, *w1, *w2, *we;
    cudaGetSymbolAddress((void**)&x,    g_x);
    cudaGetSymbolAddress((void**)&xh,   g_xh);
    cudaGetSymbolAddress((void**)&qkv,  g_qkv);
    cudaGetSymbolAddress((void**)&ah,   g_ah);
    cudaGetSymbolAddress((void**)&tmp,  g_tmp);
    cudaGetSymbolAddress((void**)&fh,   g_fh);
    cudaGetSymbolAddress((void**)&kv,   g_kv);
    cudaGetSymbolAddress((void**)&ks,   g_ks);
    cudaGetSymbolAddress((void**)&ih,   g_ih);
    cudaGetSymbolAddress((void**)&x0,   g_x0);
    cudaGetSymbolAddress((void**)&xh0,  g_xh0);
    cudaGetSymbolAddress((void**)&xg0,  g_xg0);
    cudaGetSymbolAddress((void**)&q0,   g_q0);
    cudaGetSymbolAddress((void**)&ah0,  g_ah0);
    cudaGetSymbolAddress((void**)&tmp0, g_tmp0);
    cudaGetSymbolAddress((void**)&fh0,  g_fh0);
    cudaGetSymbolAddress((void**)&bqkv, g_bqkv);
    cudaGetSymbolAddress((void**)&wqkv, g_wqkv);
    cudaGetSymbolAddress((void**)&wo,   g_wo);
    cudaGetSymbolAddress((void**)&w1,   g_w1);
    cudaGetSymbolAddress((void**)&w2,   g_w2);
    cudaGetSymbolAddress((void**)&we,   g_we);

    // ins convert
    {
        int n4 = (Bc * Sc * OBSc) / 4;
        fcvt<<<(n4 + 255) / 256, 256>>>(ins, ih, n4);
    }
    // all weight conversions (transpose + fp16 + B-fragment swizzle)
    {
        WJobs jobs;
        int nj = 0;
        jobs.j[nj++] = { W_emb, we, OBSc, Dc };
        for (int l = 0; l < Lc; l++) {
            size_t od = (size_t)l * Dc * Dc;
            size_t oq = (size_t)l * QS * Dc;
            size_t o1 = (size_t)l * Fc * Dc;
            size_t o2 = (size_t)l * Dc * Fc;
            jobs.j[nj++] = { Wq + od, wqkv + oq,                       Dc, Dc };
            jobs.j[nj++] = { Wk + od, wqkv + oq + (size_t)Dc * Dc,     Dc, Dc };
            jobs.j[nj++] = { Wv + od, wqkv + oq + (size_t)2 * Dc * Dc, Dc, Dc };
            jobs.j[nj++] = { Wo + od, wo + od, Dc, Dc };
            jobs.j[nj++] = { W1 + o1, w1 + o1, Dc, Fc };
            jobs.j[nj++] = { W2 + o2, w2 + o2, Fc, Dc };
        }
        wconv_all<<<dim3(1024, 1, 25), dim3(32, 8)>>>(jobs);
    }
    // pack qkv biases
    bpack<<<Lc, Dc>>>(bq, bk, bv, bqkv);

    // embedding GEMM (grid: x=m-blocks, y=n-blocks)
    gemm_mma<<<dim3((Bc * Sc) / 128, Dc / 128), 256, GSMEM>>>(
        ih, we, b_emb, x, xh, Bc * Sc, Dc, OBSc, Dc, 0, 1);

    // hidden-state rows
    init_h0<<<Bc, Dc>>>(hs, rsts, x, xh);

    const int MB = (Tc + 127) / 128;              // 257 m-blocks
    const dim3 gQKV(MB, QS / 128);                // (257, 12)
    const dim3 gKV (MB, 1024 / 128);              // (257, 8)
    const dim3 gD  (MB, Dc / 128);                // (257, 4)
    const dim3 gF  (MB, Fc / 128);                // (257, 16)

    // ---- layers 0..2: full ----
    for (int l = 0; l < Lc - 1; l++) {
        size_t od = (size_t)l * Dc * Dc;
        size_t oq = (size_t)l * QS * Dc;
        size_t o1 = (size_t)l * Fc * Dc;
        size_t o2 = (size_t)l * Dc * Fc;

        gemm_mma<<<gQKV, 256, GSMEM>>>(xh, wqkv + oq, bqkv + l * QS,
                                       0, qkv, Tc, QS, Dc, QS, 0, 0);

        favor_kv<<<Bc * Hc, 256>>>(qkv, kv, ks);
        favor_num<<<dim3(Bc * Hc, (SP + 15) / 16), 256>>>(qkv, kv, ks, ah);

        gemm_mma<<<gD, 256, GSMEM>>>(ah, wo + od, bo + l*Dc, tmp, 0, Tc, Dc, Dc, Dc, 0, 0);
        add_ln<<<Tc, 128>>>(tmp, x, xh, ln1s + l*Dc, ln1b + l*Dc);

        gemm_mma<<<gF, 256, GSMEM>>>(xh, w1 + o1, b1 + l*Fc, 0, fh, Tc, Fc, Dc, Fc, 1, 0);
        gemm_mma<<<gD, 256, GSMEM>>>(fh, w2 + o2, b2 + l*Dc, tmp, 0, Tc, Dc, Fc, Dc, 0, 0);
        add_ln<<<Tc, 128>>>(tmp, x, xh, ln2s + l*Dc, ln2b + l*Dc);
    }

    // ---- layer 3: only token-0 rows beyond the KV projection ----
    {
        const int l = Lc - 1;
        size_t od = (size_t)l * Dc * Dc;
        size_t oq = (size_t)l * QS * Dc;
        size_t o1 = (size_t)l * Fc * Dc;
        size_t o2 = (size_t)l * Dc * Fc;

        // K,V for all tokens (n-slice of packed QKV weights)
        gemm_mma<<<gKV, 256, GSMEM>>>(xh, wqkv + oq + (size_t)Dc * Dc,
                                      bqkv + l * QS + Dc,
                                      0, qkv + Dc, Tc, 1024, Dc, QS, 0, 0);
        // Q for the 64 token-0 rows: gather + small GEMM
        gather_x0<<<Bc, 256>>>(xh, xg0);
        gemm_mma<<<dim3(1, Dc / 128), 256, GSMEM>>>(
            xg0, wqkv + oq, bqkv + l * QS, q0, 0, Bc, Dc, Dc, Dc, 0, 0);

        favor_kv<<<Bc * Hc, 256>>>(qkv, kv, ks);
        favor_num0<<<Bc * Hc, 64>>>(q0, kv, ks, ah0);

        // AO on 64 rows
        gemm_mma<<<dim3(1, Dc / 128), 256, GSMEM>>>(
            ah0, wo + od, bo + l*Dc, tmp0, 0, Bc, Dc, Dc, Dc, 0, 0);
        add_ln0<<<Bc, 128>>>(tmp0, x, (size_t)SP * Dc, x0, xh0,
                             ln1s + l*Dc, ln1b + l*Dc);

        // FFN on 64 rows
        gemm_mma<<<dim3(1, Fc / 128), 256, GSMEM>>>(
            xh0, w1 + o1, b1 + l*Fc, 0, fh0, Bc, Fc, Dc, Fc, 1, 0);
        gemm_mma<<<dim3(1, Dc / 128), 256, GSMEM>>>(
            fh0, w2 + o2, b2 + l*Dc, tmp0, 0, Bc, Dc, Fc, Dc, 0, 0);
        add_ln0<<<Bc, 128>>>(tmp0, x0, (size_t)Dc, x0, xh0,
                             ln2s + l*Dc, ln2b + l*Dc);
    }

    head_kernel<<<Bc, Dc>>>(x0, Wqp, bqp, out);
}